// round 9
// baseline (speedup 1.0000x reference)
#include <cuda_runtime.h>
#include <cuda_fp16.h>

// Problem constants (B,H,N,D,W) = (2,12,2048,128,64)
#define Bb 2
#define Hh 12
#define Nn 2048
#define Dd 128
#define Ww 64

#define BH      (Bb * Hh)          // 24
#define ROWS    (BH * Nn)          // 49152 query rows
#define ROW_U2  (Dd / 4)           // 32 x uint2 (4 fp16) per row
#define TOTAL_U2 (ROWS * ROW_U2)   // 1,572,864

#define NUM_SM   148
#define QB_TOTAL (ROWS / 8)        // 6144 query-blocks (8 queries / CTA, 1 per warp)
#define QB_PER_SM 42               // ceil(6144/148)

// fp16 copies of K and V (device-global scratch; no allocation at runtime)
__device__ uint2 g_k16[TOTAL_U2];
__device__ uint2 g_v16[TOTAL_U2];

// ---------------------------------------------------------------------------
// Kernel 1: convert K,V fp32 -> fp16 (vectorized float4 -> 4 halves)
// ---------------------------------------------------------------------------
__global__ void __launch_bounds__(256) cvt_kernel(const float4* __restrict__ k,
                                                  const float4* __restrict__ v) {
    int i = blockIdx.x * blockDim.x + threadIdx.x;
    if (i >= TOTAL_U2) return;
    float4 a = k[i];
    __half2 h0 = __floats2half2_rn(a.x, a.y);
    __half2 h1 = __floats2half2_rn(a.z, a.w);
    uint2 u;
    u.x = *reinterpret_cast<unsigned int*>(&h0);
    u.y = *reinterpret_cast<unsigned int*>(&h1);
    g_k16[i] = u;
    float4 b = v[i];
    h0 = __floats2half2_rn(b.x, b.y);
    h1 = __floats2half2_rn(b.z, b.w);
    u.x = *reinterpret_cast<unsigned int*>(&h0);
    u.y = *reinterpret_cast<unsigned int*>(&h1);
    g_v16[i] = u;
}

// ---------------------------------------------------------------------------
// Butterfly fold: 32 lanes each hold p[0..31] (lane's 4-dim partial of score w)
// -> after 5 halving exchange steps, lane l holds the full sum for w = l.
// Step with mask M: lane keeps the half of its array whose w-bit matches its
// own lane bit, and receives the partner's partial for exactly those w's.
// ---------------------------------------------------------------------------
template <int M>
__device__ __forceinline__ void fold_step(float* p, unsigned lane) {
    const bool hi = (lane & M) != 0;
#pragma unroll
    for (int i = 0; i < M; ++i) {
        float keep = hi ? p[i + M] : p[i];
        float send = hi ? p[i] : p[i + M];
        p[i] = keep + __shfl_xor_sync(0xffffffffu, send, M);
    }
}

__device__ __forceinline__ float fold_reduce32(float* p, unsigned lane) {
    fold_step<16>(p, lane);
    fold_step<8>(p, lane);
    fold_step<4>(p, lane);
    fold_step<2>(p, lane);
    fold_step<1>(p, lane);
    return p[0];
}

// One score pass over 32 columns: column index broadcast from lane w, all 32
// lanes cooperatively load the 256B fp16 K row (perfectly coalesced LDG.64s).
__device__ __forceinline__ float score_pass(const uint2* __restrict__ kb,
                                            int c, float4 q4, unsigned lane) {
    float p[32];
#pragma unroll
    for (int w = 0; w < 32; ++w) {
        int col = __shfl_sync(0xffffffffu, c, w);
        uint2 kk = kb[col * ROW_U2];
        float2 f0 = __half22float2(*reinterpret_cast<const __half2*>(&kk.x));
        float2 f1 = __half22float2(*reinterpret_cast<const __half2*>(&kk.y));
        p[w] = fmaf(q4.x, f0.x, fmaf(q4.y, f0.y, fmaf(q4.z, f1.x, q4.w * f1.y)));
    }
    return fold_reduce32(p, lane);
}

// ---------------------------------------------------------------------------
// Kernel 2: attention. One warp per query row; 8 warps / CTA.
// Block->query swizzle: blocks equal mod 148 land on the same SM
// (LUT_classic[bid % 148]), so give them consecutive query blocks -> each SM
// stays inside one (b,h)'s 1MB fp16 K/V working set for L1 reuse.
// ---------------------------------------------------------------------------
__global__ void __launch_bounds__(256) attn_kernel(const float* __restrict__ q,
                                                   const int* __restrict__ col_ids,
                                                   float* __restrict__ out) {
    int qb = (int)(blockIdx.x % NUM_SM) * QB_PER_SM + (int)(blockIdx.x / NUM_SM);
    if (qb >= QB_TOTAL) return;

    const int warp = threadIdx.x >> 5;
    const unsigned lane = threadIdx.x & 31u;
    const int g = qb * 8 + warp;          // global query row in [0, 49152)
    const int n = g & (Nn - 1);           // sequence position (col_ids row)
    const int bh = g >> 11;               // (b*H + h)

    const uint2* __restrict__ kb = g_k16 + (size_t)bh * (Nn * ROW_U2) + lane;
    const uint2* __restrict__ vb = g_v16 + (size_t)bh * (Nn * ROW_U2) + lane;

    // q row: lane owns dims [4*lane, 4*lane+4)
    const float4 q4 = reinterpret_cast<const float4*>(q)[(size_t)g * ROW_U2 + lane];

    // lane l holds col_ids[n][l] and col_ids[n][l+32]
    const int* crow = col_ids + n * Ww;
    const int c0 = crow[lane];
    const int c1 = crow[lane + 32];
    const unsigned FULL = 0xffffffffu;

    // ---- scores (two 32-wide passes; lane l ends with s_l and s_{l+32}) ----
    float sA = score_pass(kb, c0, q4, lane);
    float sB = score_pass(kb, c1, q4, lane);

    // ---- softmax over 64 (distributed 2 per lane) ----
    const float scale = 0.08838834764831843f;   // 1/sqrt(128)
    float a = sA * scale;
    float b = sB * scale;
    float mx = fmaxf(a, b);
#pragma unroll
    for (int o = 16; o > 0; o >>= 1) mx = fmaxf(mx, __shfl_xor_sync(FULL, mx, o));
    const float eA = __expf(a - mx);
    const float eB = __expf(b - mx);
    float sm = eA + eB;
#pragma unroll
    for (int o = 16; o > 0; o >>= 1) sm += __shfl_xor_sync(FULL, sm, o);
    const float inv = __fdividef(1.0f, sm);
    const float pA = eA * inv;
    const float pB = eB * inv;

    // ---- output: out[d] = sum_w p_w * v[col_w][d], lane owns 4 dims ----
    float o0 = 0.f, o1 = 0.f, o2 = 0.f, o3 = 0.f;
#pragma unroll
    for (int w = 0; w < Ww; ++w) {
        const float pw = __shfl_sync(FULL, (w < 32) ? pA : pB, w & 31);
        const int col = __shfl_sync(FULL, (w < 32) ? c0 : c1, w & 31);
        uint2 vv = vb[col * ROW_U2];
        float2 f0 = __half22float2(*reinterpret_cast<const __half2*>(&vv.x));
        float2 f1 = __half22float2(*reinterpret_cast<const __half2*>(&vv.y));
        o0 = fmaf(pw, f0.x, o0);
        o1 = fmaf(pw, f0.y, o1);
        o2 = fmaf(pw, f1.x, o2);
        o3 = fmaf(pw, f1.y, o3);
    }

    float4 r = make_float4(o0, o1, o2, o3);
    reinterpret_cast<float4*>(out)[(size_t)g * ROW_U2 + lane] = r;
}

// ---------------------------------------------------------------------------
// Launch. Inputs (metadata order): q f32, k f32, v f32, col_ids i32.
// Output: f32 (B,H,N,D).
// ---------------------------------------------------------------------------
extern "C" void kernel_launch(void* const* d_in, const int* in_sizes, int n_in,
                              void* d_out, int out_size) {
    const float* q = (const float*)d_in[0];
    const float* k = (const float*)d_in[1];
    const float* v = (const float*)d_in[2];
    const int* col = (const int*)d_in[3];
    float* out = (float*)d_out;

    // Kernels use no shared memory; ask for max L1 carveout (ignore errors).
    (void)cudaFuncSetAttribute(attn_kernel,
                               cudaFuncAttributePreferredSharedMemoryCarveout,
                               cudaSharedmemCarveoutMaxL1);

    cvt_kernel<<<(TOTAL_U2 + 255) / 256, 256>>>((const float4*)k, (const float4*)v);
    attn_kernel<<<NUM_SM * QB_PER_SM, 256>>>(q, col, out);
}